// round 6
// baseline (speedup 1.0000x reference)
#include <cuda_runtime.h>
#include <cuda_bf16.h>
#include <stdint.h>
#include <math.h>

#define B_ROWS 65536
#define DIM    512
#define KTOT   1024            /* [Uh | Ul] x [Zh | Zl] diagonal split */
#define BD     (B_ROWS * DIM)
#define EPSF   1e-15f
#define MAXN   0.996f
#define CLIPA  (1.0f - 1e-7f)

// ------------------------------------------------------------------
// Static scratch
// ------------------------------------------------------------------
__device__ __align__(16) __nv_bfloat16 g_ub[(size_t)B_ROWS * KTOT]; // A' [B][1024]
__device__ __align__(16) __nv_bfloat16 g_zb[DIM * KTOT];            // B' [out j][1024]
__device__ float g_cu2[B_ROWS];
__device__ float g_x2c[B_ROWS];
__device__ __align__(16) float g_c1[DIM];   // 2*cosh(2b)/zn
__device__ __align__(16) float g_c2[DIM];   // sinh(2b)
__device__ __align__(16) float g_s2[DIM];   // 2*zn

// ------------------------------------------------------------------
// Fast math (MUFU-based)
// ------------------------------------------------------------------
__device__ __forceinline__ float f_rcp(float x){ float y; asm("rcp.approx.f32 %0,%1;" : "=f"(y) : "f"(x)); return y; }
__device__ __forceinline__ float f_lg2(float x){ float y; asm("lg2.approx.f32 %0,%1;" : "=f"(y) : "f"(x)); return y; }
__device__ __forceinline__ float f_ex2(float x){ float y; asm("ex2.approx.f32 %0,%1;" : "=f"(y) : "f"(x)); return y; }
__device__ __forceinline__ float f_sqrt(float x){ float y; asm("sqrt.approx.f32 %0,%1;" : "=f"(y) : "f"(x)); return y; }

__device__ __forceinline__ float atanh_f(float x){
    return 0.34657359028f * f_lg2((1.f + x) * f_rcp(1.f - x));
}
__device__ __forceinline__ float tanh_f(float x){
    return 1.f - 2.f * f_rcp(f_ex2(x * 2.88539008178f) + 1.f);
}
__device__ __forceinline__ float sigmoid_f(float x){
    return f_rcp(1.f + f_ex2(-1.44269504089f * x));
}
__device__ __forceinline__ float sinh_asinh(float t, float s){
    float a = fabsf(t);
    float q = a + f_sqrt(fmaf(a, a, 1.f));
    float p = f_ex2(s * f_lg2(q));
    return copysignf(0.5f * (p - f_rcp(p)), t);
}

// ------------------------------------------------------------------
// Portable tensor-core primitives (sm_80 feature set)
// ------------------------------------------------------------------
__device__ __forceinline__ uint32_t s2u(const void* p){ return (uint32_t)__cvta_generic_to_shared(p); }

__device__ __forceinline__ void cp16(uint32_t dst, const void* src){
    asm volatile("cp.async.cg.shared.global [%0], [%1], 16;" :: "r"(dst), "l"(src));
}
__device__ __forceinline__ void cp_commit(){ asm volatile("cp.async.commit_group;" ::: "memory"); }
template<int N> __device__ __forceinline__ void cp_wait(){ asm volatile("cp.async.wait_group %0;" :: "n"(N) : "memory"); }

__device__ __forceinline__ void ldsm4(uint32_t* r, uint32_t addr){
    asm volatile("ldmatrix.sync.aligned.m8n8.x4.shared.b16 {%0,%1,%2,%3}, [%4];"
        : "=r"(r[0]),"=r"(r[1]),"=r"(r[2]),"=r"(r[3]) : "r"(addr));
}
__device__ __forceinline__ void mma16816(float* c, const uint32_t* a, uint32_t b0, uint32_t b1){
    asm volatile("mma.sync.aligned.m16n8k16.row.col.f32.bf16.bf16.f32 "
        "{%0,%1,%2,%3}, {%4,%5,%6,%7}, {%8,%9}, {%0,%1,%2,%3};"
        : "+f"(c[0]),"+f"(c[1]),"+f"(c[2]),"+f"(c[3])
        : "r"(a[0]),"r"(a[1]),"r"(a[2]),"r"(a[3]), "r"(b0),"r"(b1));
}

// ------------------------------------------------------------------
// Kernel 1: z stats + transposed bf16 split of z into B' = [Zh|Zl]
// ------------------------------------------------------------------
__global__ void prep_cols(const float* __restrict__ z, const float* __restrict__ bias){
    __shared__ float sb[4];
    int j = blockIdx.x, t = threadIdx.x;
    float s = 0.f;
    for (int i = t; i < DIM; i += 128){
        float v = z[i * DIM + j];
        s += v * v;
        __nv_bfloat16 h = __float2bfloat16(v);
        __nv_bfloat16 lo = __float2bfloat16(v - __bfloat162float(h));
        g_zb[j * KTOT + i]       = h;
        g_zb[j * KTOT + DIM + i] = lo;
    }
#pragma unroll
    for (int o = 16; o; o >>= 1) s += __shfl_down_sync(0xffffffffu, s, o);
    if ((t & 31) == 0) sb[t >> 5] = s;
    __syncthreads();
    if (t == 0){
        float tot = sb[0] + sb[1] + sb[2] + sb[3];
        float zn = sqrtf(fmaxf(tot, EPSF));
        float tb = 2.f * bias[j];
        g_c1[j] = 2.f * coshf(tb) / zn;
        g_c2[j] = sinhf(tb);
        g_s2[j] = 2.f * zn;
    }
}

// ------------------------------------------------------------------
// Kernel 2: warp-per-row: u = expmap0(logmap(xp,xc)) -> A' = [Uh|Ul]
// ------------------------------------------------------------------
__global__ void __launch_bounds__(256) prep_rows(const float* __restrict__ xc_g,
                                                 const float* __restrict__ xp_g){
    int row = blockIdx.x * 8 + (threadIdx.x >> 5);
    int l   = threadIdx.x & 31;
    const float4* xc4 = (const float4*)(xc_g + (size_t)row * DIM);
    const float4* xp4 = (const float4*)(xp_g + (size_t)row * DIM);

    float4 xc[4], xp[4];
    float px2 = 0.f, py2 = 0.f, pxy = 0.f;
#pragma unroll
    for (int i = 0; i < 4; i++){
        xc[i] = xc4[i * 32 + l];
        xp[i] = xp4[i * 32 + l];
        px2 += xp[i].x*xp[i].x + xp[i].y*xp[i].y + xp[i].z*xp[i].z + xp[i].w*xp[i].w;
        py2 += xc[i].x*xc[i].x + xc[i].y*xc[i].y + xc[i].z*xc[i].z + xc[i].w*xc[i].w;
        pxy += xp[i].x*xc[i].x + xp[i].y*xc[i].y + xp[i].z*xc[i].z + xp[i].w*xc[i].w;
    }
#pragma unroll
    for (int o = 16; o; o >>= 1){
        px2 += __shfl_xor_sync(0xffffffffu, px2, o);
        py2 += __shfl_xor_sync(0xffffffffu, py2, o);
        pxy += __shfl_xor_sync(0xffffffffu, pxy, o);
    }
    float fA = 1.f - 2.f * pxy + py2;
    float fB = 1.f - px2;
    float invden = f_rcp(fmaxf(1.f - 2.f * pxy + px2 * py2, EPSF));

    float4 sub[4];
    float psn2 = 0.f;
#pragma unroll
    for (int i = 0; i < 4; i++){
        sub[i].x = (fB * xc[i].x - fA * xp[i].x) * invden;
        sub[i].y = (fB * xc[i].y - fA * xp[i].y) * invden;
        sub[i].z = (fB * xc[i].z - fA * xp[i].z) * invden;
        sub[i].w = (fB * xc[i].w - fA * xp[i].w) * invden;
        psn2 += sub[i].x*sub[i].x + sub[i].y*sub[i].y + sub[i].z*sub[i].z + sub[i].w*sub[i].w;
    }
#pragma unroll
    for (int o = 16; o; o >>= 1) psn2 += __shfl_xor_sync(0xffffffffu, psn2, o);
    float sn2 = psn2;
    float sn  = f_sqrt(fmaxf(sn2, EPSF));
    float c   = fmaxf(fB, EPSF) * atanh_f(fminf(sn, CLIPA)) * f_rcp(sn);
    float un  = f_sqrt(fmaxf(c * c * sn2, EPSF));
    float s   = tanh_f(un) * c * f_rcp(un);

    uint2* ub = (uint2*)(g_ub + (size_t)row * KTOT);
#pragma unroll
    for (int i = 0; i < 4; i++){
        float u0 = s*sub[i].x, u1 = s*sub[i].y, u2 = s*sub[i].z, u3 = s*sub[i].w;
        __nv_bfloat16 h0=__float2bfloat16(u0), h1=__float2bfloat16(u1),
                      h2=__float2bfloat16(u2), h3=__float2bfloat16(u3);
        __nv_bfloat16 l0=__float2bfloat16(u0-__bfloat162float(h0)),
                      l1=__float2bfloat16(u1-__bfloat162float(h1)),
                      l2=__float2bfloat16(u2-__bfloat162float(h2)),
                      l3=__float2bfloat16(u3-__bfloat162float(h3));
        uint2 hv, lv;
        hv.x = (uint32_t)__bfloat16_as_ushort(h0) | ((uint32_t)__bfloat16_as_ushort(h1) << 16);
        hv.y = (uint32_t)__bfloat16_as_ushort(h2) | ((uint32_t)__bfloat16_as_ushort(h3) << 16);
        lv.x = (uint32_t)__bfloat16_as_ushort(l0) | ((uint32_t)__bfloat16_as_ushort(l1) << 16);
        lv.y = (uint32_t)__bfloat16_as_ushort(l2) | ((uint32_t)__bfloat16_as_ushort(l3) << 16);
        int q = i * 32 + l;
        ub[q]       = hv;   // Uh @ [0,512)
        ub[128 + q] = lv;   // Ul @ [512,1024)
    }
    if (l == 0){
        g_cu2[row] = s * s * sn2;
        g_x2c[row] = py2;
    }
}

// ------------------------------------------------------------------
// Kernel 3 (FUSED): GEMM (BM=64 x full N=512) + poincare_fc epilogue +
// expmap/residual/projections, writing final outputs. 512 threads,
// 16 warps (4/SMSP), 3-stage cp.async.
// ------------------------------------------------------------------
#define FBM 64
#define FBK 64
#define FA_BYTES (FBM*FBK*2)               /* 8192  */
#define FB_BYTES (DIM*FBK*2)               /* 65536 */
#define FSTAGE   (FA_BYTES + FB_BYTES)     /* 73728 */
#define FNSTAGE  3
#define FSM_TOT  (FNSTAGE * FSTAGE)        /* 221184 */
#define FNKT     (KTOT / FBK)              /* 16 */
#define XC_PITCH 520                        /* padded floats per row */

__global__ void __launch_bounds__(512, 1) fused_gemm(
        const float* __restrict__ xc_g,
        const float* __restrict__ alpha_p,
        const float* __restrict__ step_p,
        float* __restrict__ out){
    extern __shared__ __align__(128) char sm[];
    uint32_t sb = s2u(sm);
    int tid = threadIdx.x;
    int wid = tid >> 5, lane = tid & 31;
    int m0 = blockIdx.x * FBM;
    int wm = wid & 1;        // 2 warps over M (32 rows each)
    int wn = wid >> 1;       // 8 warps over N (64 cols each)

    const char* gA = (const char*)g_ub;
    const char* gB = (const char*)g_zb;

    float acc[2][8][4];
#pragma unroll
    for (int i=0;i<2;i++)
#pragma unroll
        for (int j=0;j<8;j++)
#pragma unroll
            for (int k=0;k<4;k++) acc[i][j][k] = 0.f;

#define FLOAD(s, kt) do {                                                      \
        uint32_t base_ = sb + (s) * FSTAGE;                                    \
        size_t k0_ = (size_t)(kt) * FBK;                                       \
        {   /* A: 64 rows x 8 chunks = 512 cp16, 1 per thread */               \
            int r_ = tid >> 3, c_ = tid & 7;                                   \
            uint32_t so_ = base_ + r_ * 128 + ((c_ ^ (r_ & 7)) << 4);          \
            cp16(so_, gA + ((size_t)(m0 + r_) * KTOT + k0_) * 2 + (c_ << 4));  \
        }                                                                      \
        _Pragma("unroll")                                                      \
        for (int it = 0; it < 8; it++){   /* B: 512 rows x 8 chunks */         \
            int idx_ = it * 512 + tid;                                         \
            int r_ = idx_ >> 3, c_ = idx_ & 7;                                 \
            uint32_t so_ = base_ + FA_BYTES + r_ * 128 + ((c_ ^ (r_ & 7)) << 4);\
            cp16(so_, gB + ((size_t)r_ * KTOT + k0_) * 2 + (c_ << 4));         \
        }                                                                      \
    } while (0)

    FLOAD(0, 0); cp_commit();
    FLOAD(1, 1); cp_commit();

    int lrow = lane & 15;
    int khalf = lane >> 4;

#pragma unroll 1
    for (int kt = 0; kt < FNKT; kt++){
        cp_wait<1>();
        __syncthreads();
        if (kt + 2 < FNKT){ FLOAD((kt + 2) % 3, kt + 2); }
        cp_commit();

        uint32_t aBase = sb + (kt % 3) * FSTAGE;
        uint32_t bBase = aBase + FA_BYTES;
#pragma unroll
        for (int ks = 0; ks < 4; ks++){
            int c16 = ks * 2 + khalf;
            uint32_t a[2][4], bb[4][4];
#pragma unroll
            for (int i = 0; i < 2; i++){
                int row = wm * 32 + i * 16 + lrow;
                ldsm4(a[i], aBase + row * 128 + ((c16 ^ (row & 7)) << 4));
            }
#pragma unroll
            for (int j = 0; j < 4; j++){
                int row = wn * 64 + j * 16 + lrow;
                ldsm4(bb[j], bBase + row * 128 + ((c16 ^ (row & 7)) << 4));
            }
#pragma unroll
            for (int mi = 0; mi < 2; mi++)
#pragma unroll
                for (int ni = 0; ni < 8; ni++)
                    mma16816(acc[mi][ni], a[mi], bb[ni >> 1][ni & 1], bb[ni >> 1][(ni & 1) + 2]);
        }
    }

    // ---------------- fused epilogue ----------------
    __syncthreads();     // mainloop smem dead; reuse for xc tile + reductions

    float* sm_xc  = (float*)sm;                              // [64][520]
    float* sm_red = (float*)(sm + 64 * XC_PITCH * 4);        // [64][16] (w2 | xw)
    float* sm_row = (float*)(sm + 64 * XC_PITCH * 4 + 4096); // [64][4] CA,CB,fxc

    // stage xc tile into smem (coalesced float4)
    {
        const float4* xs = (const float4*)(xc_g + (size_t)m0 * DIM);
#pragma unroll
        for (int j = tid; j < FBM * DIM / 4; j += 512){
            int row = j >> 7, c4 = j & 127;
            *(float4*)&sm_xc[row * XC_PITCH + c4 * 4] = xs[j];
        }
    }
    __syncthreads();

    // per-row constants for this thread's 4 rows (mi, epair)
    int qrow = lane >> 2;            // 0..7
    int qcol = (lane & 3) * 2;       // 0,2,4,6
    float opv[4], idv[4];
#pragma unroll
    for (int mi = 0; mi < 2; mi++)
#pragma unroll
        for (int ep = 0; ep < 2; ep++){
            int r = wm * 32 + mi * 16 + ep * 8 + qrow;
            float cu2 = g_cu2[m0 + r];
            opv[mi*2+ep] = 1.f + cu2;
            idv[mi*2+ep] = f_rcp(fmaxf(1.f - cu2, EPSF));
        }

    // w = sinh_asinh(...) in place; partial row sums
    float pw2[4] = {0.f,0.f,0.f,0.f}, pxw[4] = {0.f,0.f,0.f,0.f};
#pragma unroll
    for (int ni = 0; ni < 8; ni++){
        int col = wn * 64 + ni * 8 + qcol;
        float2 c1v = *(const float2*)&g_c1[col];
        float2 c2v = *(const float2*)&g_c2[col];
        float2 s2v = *(const float2*)&g_s2[col];
#pragma unroll
        for (int mi = 0; mi < 2; mi++){
#pragma unroll
            for (int ep = 0; ep < 2; ep++){
                int q = mi*2 + ep;
                int r = wm * 32 + mi * 16 + ep * 8 + qrow;
                float t0 = (acc[mi][ni][ep*2+0] * c1v.x - opv[q] * c2v.x) * idv[q];
                float t1 = (acc[mi][ni][ep*2+1] * c1v.y - opv[q] * c2v.y) * idv[q];
                float w0 = sinh_asinh(t0, s2v.x);
                float w1 = sinh_asinh(t1, s2v.y);
                acc[mi][ni][ep*2+0] = w0;
                acc[mi][ni][ep*2+1] = w1;
                float xc0 = sm_xc[r * XC_PITCH + col];
                float xc1 = sm_xc[r * XC_PITCH + col + 1];
                pw2[q] = fmaf(w0, w0, fmaf(w1, w1, pw2[q]));
                pxw[q] = fmaf(xc0, w0, fmaf(xc1, w1, pxw[q]));
            }
        }
    }
    // quad reduce (lanes sharing the same row)
#pragma unroll
    for (int q = 0; q < 4; q++){
#pragma unroll
        for (int o = 1; o < 4; o <<= 1){
            pw2[q] += __shfl_xor_sync(0xffffffffu, pw2[q], o);
            pxw[q] += __shfl_xor_sync(0xffffffffu, pxw[q], o);
        }
    }
    if ((lane & 3) == 0){
#pragma unroll
        for (int mi = 0; mi < 2; mi++)
#pragma unroll
            for (int ep = 0; ep < 2; ep++){
                int r = wm * 32 + mi * 16 + ep * 8 + qrow;
                sm_red[r * 16 + wn]     = pw2[mi*2+ep];
                sm_red[r * 16 + 8 + wn] = pxw[mi*2+ep];
            }
    }
    __syncthreads();

    // per-row scalar chain (threads 0..63)
    if (tid < FBM){
        int r = tid;
        float w2s = 0.f, xw = 0.f;
#pragma unroll
        for (int j = 0; j < 8; j++){
            w2s += sm_red[r * 16 + j];
            xw  += sm_red[r * 16 + 8 + j];
        }
        float x2 = g_x2c[m0 + r];

        float gg  = 1.f + f_sqrt(1.f + w2s);
        float rg  = f_rcp(gg);
        float yn  = f_sqrt(fmaxf(w2s * rg * rg, EPSF));
        float kv  = atanh_f(fminf(yn, CLIPA)) * f_rcp(yn);
        float step = sigmoid_f(step_p[0]);
        float m0s = step * kv * rg;
        float un  = f_sqrt(fmaxf(m0s * m0s * w2s, EPSF));
        float lam = 2.f * f_rcp(fmaxf(1.f - x2, EPSF));
        float mt  = tanh_f(0.5f * lam * un) * m0s * f_rcp(un);

        float t2s = mt * mt * w2s;
        float xt  = mt * xw;
        float pp  = 1.f + 2.f * xt + t2s;
        float qq  = 1.f - x2;
        float id2 = f_rcp(fmaxf(1.f + 2.f * xt + x2 * t2s, EPSF));
        float a1  = pp * id2, b1 = qq * mt * id2;

        float nxu2 = a1*a1*x2 + 2.f*a1*b1*xw + b1*b1*w2s;
        float nxu  = f_sqrt(fmaxf(nxu2, EPSF));
        float fxu  = (nxu > MAXN) ? MAXN * f_rcp(nxu) : 1.f;
        a1 *= fxu; b1 *= fxu;
        float nxup = fminf(nxu, MAXN);

        float nxc  = f_sqrt(fmaxf(x2, EPSF));
        float fxc  = (nxc > MAXN) ? MAXN * f_rcp(nxc) : 1.f;
        float nxcp = fminf(nxc, MAXN);

        float aa  = sigmoid_f(alpha_p[0]);
        float th1 = tanh_f(aa * atanh_f(fminf(nxcp, CLIPA)));
        float A1  = th1 * f_rcp(nxcp) * fxc;
        float th2 = tanh_f((1.f - aa) * atanh_f(fminf(nxup, CLIPA)));
        float r2  = th2 * f_rcp(nxup);
        float A2  = r2 * a1, B2 = r2 * b1;

        float x2m = th1 * th1, y2m = th2 * th2;
        float xym = A1 * (A2 * x2 + B2 * xw);
        float P   = 1.f + 2.f * xym + y2m;
        float Q   = 1.f - x2m;
        float id3 = f_rcp(fmaxf(1.f + 2.f * xym + x2m * y2m, EPSF));
        float CA  = (P * A1 + Q * A2) * id3;
        float CB  = (Q * B2) * id3;

        float nn2 = CA*CA*x2 + 2.f*CA*CB*xw + CB*CB*w2s;
        float nn  = f_sqrt(fmaxf(nn2, EPSF));
        float fo  = (nn > MAXN) ? MAXN * f_rcp(nn) : 1.f;
        CA *= fo; CB *= fo;

        sm_row[r * 4 + 0] = CA;
        sm_row[r * 4 + 1] = CB;
        sm_row[r * 4 + 2] = fxc;
    }
    __syncthreads();

    // write outputs
#pragma unroll
    for (int mi = 0; mi < 2; mi++){
#pragma unroll
        for (int ep = 0; ep < 2; ep++){
            int r = wm * 32 + mi * 16 + ep * 8 + qrow;
            float CA  = sm_row[r * 4 + 0];
            float CB  = sm_row[r * 4 + 1];
            float fxc = sm_row[r * 4 + 2];
            float* o1p = out + (size_t)(m0 + r) * DIM;
            float* o2p = out + (size_t)BD + (size_t)(m0 + r) * DIM;
#pragma unroll
            for (int ni = 0; ni < 8; ni++){
                int col = wn * 64 + ni * 8 + qcol;
                float xc0 = sm_xc[r * XC_PITCH + col];
                float xc1 = sm_xc[r * XC_PITCH + col + 1];
                float w0 = acc[mi][ni][ep*2+0];
                float w1 = acc[mi][ni][ep*2+1];
                *(float2*)(o1p + col) = make_float2(fmaf(CA, xc0, CB * w0),
                                                    fmaf(CA, xc1, CB * w1));
                *(float2*)(o2p + col) = make_float2(fxc * xc0, fxc * xc1);
            }
        }
    }
}

// ------------------------------------------------------------------
extern "C" void kernel_launch(void* const* d_in, const int* in_sizes, int n_in,
                              void* d_out, int out_size) {
    const float* xc    = (const float*)d_in[0];
    const float* xp    = (const float*)d_in[1];
    const float* z     = (const float*)d_in[2];
    const float* bias  = (const float*)d_in[3];
    const float* alpha = (const float*)d_in[4];
    const float* stepz = (const float*)d_in[5];
    float* out = (float*)d_out;

    static int smem_set = 0;
    if (!smem_set){
        cudaFuncSetAttribute(fused_gemm, cudaFuncAttributeMaxDynamicSharedMemorySize,
                             FSM_TOT);
        smem_set = 1;
    }

    prep_cols<<<DIM, 128>>>(z, bias);
    prep_rows<<<B_ROWS / 8, 256>>>(xc, xp);
    fused_gemm<<<B_ROWS / FBM, 512, FSM_TOT>>>(xc, alpha, stepz, out);
}

// round 7
// speedup vs baseline: 1.1615x; 1.1615x over previous
#include <cuda_runtime.h>
#include <cuda_bf16.h>
#include <stdint.h>
#include <math.h>

#define B_ROWS 65536
#define DIM    512
#define KTOT   1024            /* [Uh | Ul] x [Zh | Zl] diagonal split */
#define BD     (B_ROWS * DIM)
#define EPSF   1e-15f
#define MAXN   0.996f
#define CLIPA  (1.0f - 1e-7f)
#define NCHUNK 4
#define CROWS  (B_ROWS / NCHUNK)   /* 16384 */

// ------------------------------------------------------------------
// Static scratch
// ------------------------------------------------------------------
__device__ __align__(16) __nv_bfloat16 g_ub[(size_t)B_ROWS * KTOT]; // A' [B][1024]
__device__ __align__(16) __nv_bfloat16 g_zb[DIM * KTOT];            // B' [out j][1024]
__device__ __align__(16) float g_inner[BD];
__device__ float g_cu2[B_ROWS];
__device__ float g_x2c[B_ROWS];
__device__ __align__(16) float g_c1[DIM];
__device__ __align__(16) float g_c2[DIM];
__device__ __align__(16) float g_s2[DIM];

// ------------------------------------------------------------------
// Fast math (MUFU-based)
// ------------------------------------------------------------------
__device__ __forceinline__ float f_rcp(float x){ float y; asm("rcp.approx.f32 %0,%1;" : "=f"(y) : "f"(x)); return y; }
__device__ __forceinline__ float f_lg2(float x){ float y; asm("lg2.approx.f32 %0,%1;" : "=f"(y) : "f"(x)); return y; }
__device__ __forceinline__ float f_ex2(float x){ float y; asm("ex2.approx.f32 %0,%1;" : "=f"(y) : "f"(x)); return y; }
__device__ __forceinline__ float f_sqrt(float x){ float y; asm("sqrt.approx.f32 %0,%1;" : "=f"(y) : "f"(x)); return y; }

__device__ __forceinline__ float atanh_f(float x){
    return 0.34657359028f * f_lg2((1.f + x) * f_rcp(1.f - x));
}
__device__ __forceinline__ float tanh_f(float x){
    return 1.f - 2.f * f_rcp(f_ex2(x * 2.88539008178f) + 1.f);
}
__device__ __forceinline__ float sigmoid_f(float x){
    return f_rcp(1.f + f_ex2(-1.44269504089f * x));
}
__device__ __forceinline__ float sinh_asinh(float t, float s){
    float a = fabsf(t);
    float q = a + f_sqrt(fmaf(a, a, 1.f));
    float p = f_ex2(s * f_lg2(q));
    return copysignf(0.5f * (p - f_rcp(p)), t);
}

// ------------------------------------------------------------------
// Portable tensor-core primitives
// ------------------------------------------------------------------
__device__ __forceinline__ uint32_t s2u(const void* p){ return (uint32_t)__cvta_generic_to_shared(p); }

__device__ __forceinline__ void cp16(uint32_t dst, const void* src){
    asm volatile("cp.async.cg.shared.global [%0], [%1], 16;" :: "r"(dst), "l"(src));
}
__device__ __forceinline__ void cp_commit(){ asm volatile("cp.async.commit_group;" ::: "memory"); }
template<int N> __device__ __forceinline__ void cp_wait(){ asm volatile("cp.async.wait_group %0;" :: "n"(N) : "memory"); }

__device__ __forceinline__ void ldsm4(uint32_t* r, uint32_t addr){
    asm volatile("ldmatrix.sync.aligned.m8n8.x4.shared.b16 {%0,%1,%2,%3}, [%4];"
        : "=r"(r[0]),"=r"(r[1]),"=r"(r[2]),"=r"(r[3]) : "r"(addr));
}
__device__ __forceinline__ void mma16816(float* c, const uint32_t* a, uint32_t b0, uint32_t b1){
    asm volatile("mma.sync.aligned.m16n8k16.row.col.f32.bf16.bf16.f32 "
        "{%0,%1,%2,%3}, {%4,%5,%6,%7}, {%8,%9}, {%0,%1,%2,%3};"
        : "+f"(c[0]),"+f"(c[1]),"+f"(c[2]),"+f"(c[3])
        : "r"(a[0]),"r"(a[1]),"r"(a[2]),"r"(a[3]), "r"(b0),"r"(b1));
}

// ------------------------------------------------------------------
// Kernel 1: z stats + transposed bf16 split of z into B' = [Zh|Zl]
// ------------------------------------------------------------------
__global__ void prep_cols(const float* __restrict__ z, const float* __restrict__ bias){
    __shared__ float sb[4];
    int j = blockIdx.x, t = threadIdx.x;
    float s = 0.f;
    for (int i = t; i < DIM; i += 128){
        float v = z[i * DIM + j];
        s += v * v;
        __nv_bfloat16 h = __float2bfloat16(v);
        __nv_bfloat16 lo = __float2bfloat16(v - __bfloat162float(h));
        g_zb[j * KTOT + i]       = h;
        g_zb[j * KTOT + DIM + i] = lo;
    }
#pragma unroll
    for (int o = 16; o; o >>= 1) s += __shfl_down_sync(0xffffffffu, s, o);
    if ((t & 31) == 0) sb[t >> 5] = s;
    __syncthreads();
    if (t == 0){
        float tot = sb[0] + sb[1] + sb[2] + sb[3];
        float zn = sqrtf(fmaxf(tot, EPSF));
        float tb = 2.f * bias[j];
        g_c1[j] = 2.f * coshf(tb) / zn;
        g_c2[j] = sinhf(tb);
        g_s2[j] = 2.f * zn;
    }
}

// ------------------------------------------------------------------
// Kernel 2: warp-per-row (chunked)
// ------------------------------------------------------------------
__global__ void __launch_bounds__(256) prep_rows(const float* __restrict__ xc_g,
                                                 const float* __restrict__ xp_g,
                                                 int row0){
    int row = row0 + blockIdx.x * 8 + (threadIdx.x >> 5);
    int l   = threadIdx.x & 31;
    const float4* xc4 = (const float4*)(xc_g + (size_t)row * DIM);
    const float4* xp4 = (const float4*)(xp_g + (size_t)row * DIM);

    float4 xc[4], xp[4];
    float px2 = 0.f, py2 = 0.f, pxy = 0.f;
#pragma unroll
    for (int i = 0; i < 4; i++){
        xc[i] = xc4[i * 32 + l];
        xp[i] = xp4[i * 32 + l];
        px2 += xp[i].x*xp[i].x + xp[i].y*xp[i].y + xp[i].z*xp[i].z + xp[i].w*xp[i].w;
        py2 += xc[i].x*xc[i].x + xc[i].y*xc[i].y + xc[i].z*xc[i].z + xc[i].w*xc[i].w;
        pxy += xp[i].x*xc[i].x + xp[i].y*xc[i].y + xp[i].z*xc[i].z + xp[i].w*xc[i].w;
    }
#pragma unroll
    for (int o = 16; o; o >>= 1){
        px2 += __shfl_xor_sync(0xffffffffu, px2, o);
        py2 += __shfl_xor_sync(0xffffffffu, py2, o);
        pxy += __shfl_xor_sync(0xffffffffu, pxy, o);
    }
    float fA = 1.f - 2.f * pxy + py2;
    float fB = 1.f - px2;
    float invden = f_rcp(fmaxf(1.f - 2.f * pxy + px2 * py2, EPSF));

    float4 sub[4];
    float psn2 = 0.f;
#pragma unroll
    for (int i = 0; i < 4; i++){
        sub[i].x = (fB * xc[i].x - fA * xp[i].x) * invden;
        sub[i].y = (fB * xc[i].y - fA * xp[i].y) * invden;
        sub[i].z = (fB * xc[i].z - fA * xp[i].z) * invden;
        sub[i].w = (fB * xc[i].w - fA * xp[i].w) * invden;
        psn2 += sub[i].x*sub[i].x + sub[i].y*sub[i].y + sub[i].z*sub[i].z + sub[i].w*sub[i].w;
    }
#pragma unroll
    for (int o = 16; o; o >>= 1) psn2 += __shfl_xor_sync(0xffffffffu, psn2, o);
    float sn2 = psn2;
    float sn  = f_sqrt(fmaxf(sn2, EPSF));
    float c   = fmaxf(fB, EPSF) * atanh_f(fminf(sn, CLIPA)) * f_rcp(sn);
    float un  = f_sqrt(fmaxf(c * c * sn2, EPSF));
    float s   = tanh_f(un) * c * f_rcp(un);

    uint2* ub = (uint2*)(g_ub + (size_t)row * KTOT);
#pragma unroll
    for (int i = 0; i < 4; i++){
        float u0 = s*sub[i].x, u1 = s*sub[i].y, u2 = s*sub[i].z, u3 = s*sub[i].w;
        __nv_bfloat16 h0=__float2bfloat16(u0), h1=__float2bfloat16(u1),
                      h2=__float2bfloat16(u2), h3=__float2bfloat16(u3);
        __nv_bfloat16 l0=__float2bfloat16(u0-__bfloat162float(h0)),
                      l1=__float2bfloat16(u1-__bfloat162float(h1)),
                      l2=__float2bfloat16(u2-__bfloat162float(h2)),
                      l3=__float2bfloat16(u3-__bfloat162float(h3));
        uint2 hv, lv;
        hv.x = (uint32_t)__bfloat16_as_ushort(h0) | ((uint32_t)__bfloat16_as_ushort(h1) << 16);
        hv.y = (uint32_t)__bfloat16_as_ushort(h2) | ((uint32_t)__bfloat16_as_ushort(h3) << 16);
        lv.x = (uint32_t)__bfloat16_as_ushort(l0) | ((uint32_t)__bfloat16_as_ushort(l1) << 16);
        lv.y = (uint32_t)__bfloat16_as_ushort(l2) | ((uint32_t)__bfloat16_as_ushort(l3) << 16);
        int q = i * 32 + l;
        ub[q]       = hv;
        ub[128 + q] = lv;
    }
    if (l == 0){
        g_cu2[row] = s * s * sn2;
        g_x2c[row] = py2;
    }
}

// ------------------------------------------------------------------
// Kernel 3: bf16 HMMA GEMM (R4 mainloop, chunked along M)
// ------------------------------------------------------------------
#define BM 128
#define BN 256
#define BK 64
#define A_BYTES (BM*BK*2)
#define B_BYTES (BN*BK*2)
#define STAGE_BYTES (A_BYTES + B_BYTES)
#define NSTAGE 3
#define NKT (KTOT / BK)

__global__ void __launch_bounds__(256, 1) gemm_mma(int row0){
    extern __shared__ __align__(128) char sm[];
    uint32_t sb = s2u(sm);
    int tid = threadIdx.x;
    int wid = tid >> 5, lane = tid & 31;
    int m0 = row0 + blockIdx.y * BM;
    int n0 = blockIdx.x * BN;
    int wm = wid & 1;
    int wn = wid >> 1;

    const char* gA = (const char*)g_ub;
    const char* gB = (const char*)g_zb;

    float acc[4][8][4];
#pragma unroll
    for (int i=0;i<4;i++)
#pragma unroll
        for (int j=0;j<8;j++)
#pragma unroll
            for (int k=0;k<4;k++) acc[i][j][k] = 0.f;

    int lr = tid >> 3;
    int lc = tid & 7;

#define LOAD_STAGE(s, kt) do {                                                 \
        uint32_t base_ = sb + (s) * STAGE_BYTES;                               \
        size_t k0_ = (size_t)(kt) * BK;                                        \
        _Pragma("unroll")                                                      \
        for (int it = 0; it < 4; it++){                                        \
            int r_ = it * 32 + lr;                                             \
            uint32_t so_ = base_ + r_ * 128 + ((lc ^ (r_ & 7)) << 4);          \
            cp16(so_, gA + ((size_t)(m0 + r_) * KTOT + k0_) * 2 + (lc << 4));  \
        }                                                                      \
        _Pragma("unroll")                                                      \
        for (int it = 0; it < 8; it++){                                        \
            int r_ = it * 32 + lr;                                             \
            uint32_t so_ = base_ + A_BYTES + r_ * 128 + ((lc ^ (r_ & 7)) << 4);\
            cp16(so_, gB + ((size_t)(n0 + r_) * KTOT + k0_) * 2 + (lc << 4));  \
        }                                                                      \
    } while (0)

    LOAD_STAGE(0, 0); cp_commit();
    LOAD_STAGE(1, 1); cp_commit();

    int lrow = lane & 15;
    int khalf = lane >> 4;

#pragma unroll 1
    for (int kt = 0; kt < NKT; kt++){
        cp_wait<1>();
        __syncthreads();
        uint32_t aBase = sb + (kt % 3) * STAGE_BYTES;
        uint32_t bBase = aBase + A_BYTES;
#pragma unroll
        for (int ks = 0; ks < 4; ks++){
            int c16 = ks * 2 + khalf;
            uint32_t a[4][4], bb[4][4];
#pragma unroll
            for (int i = 0; i < 4; i++){
                int row = wm * 64 + i * 16 + lrow;
                ldsm4(a[i], aBase + row * 128 + ((c16 ^ (row & 7)) << 4));
            }
#pragma unroll
            for (int j = 0; j < 4; j++){
                int row = wn * 64 + j * 16 + lrow;
                ldsm4(bb[j], bBase + row * 128 + ((c16 ^ (row & 7)) << 4));
            }
#pragma unroll
            for (int mi = 0; mi < 4; mi++)
#pragma unroll
                for (int ni = 0; ni < 8; ni++)
                    mma16816(acc[mi][ni], a[mi], bb[ni >> 1][ni & 1], bb[ni >> 1][(ni & 1) + 2]);
        }
        if (kt + 2 < NKT){ LOAD_STAGE((kt + 2) % 3, kt + 2); }
        cp_commit();
        __syncthreads();
    }

    int erow = lane >> 2;
    int ecol = (lane & 3) * 2;
#pragma unroll
    for (int mi = 0; mi < 4; mi++){
#pragma unroll
        for (int ni = 0; ni < 8; ni++){
            int r = m0 + wm * 64 + mi * 16 + erow;
            int c = n0 + wn * 64 + ni * 8 + ecol;
            float* p = g_inner + (size_t)r * DIM + c;
            *(float2*)p             = make_float2(acc[mi][ni][0], acc[mi][ni][1]);
            *(float2*)(p + 8 * DIM) = make_float2(acc[mi][ni][2], acc[mi][ni][3]);
        }
    }
}

// ------------------------------------------------------------------
// Kernel 4: warp-per-row epilogue (chunked)
// ------------------------------------------------------------------
__global__ void __launch_bounds__(256) finish_rows(const float* __restrict__ xc_g,
                                                   const float* __restrict__ alpha_p,
                                                   const float* __restrict__ step_p,
                                                   float* __restrict__ out,
                                                   int row0){
    int row = row0 + blockIdx.x * 8 + (threadIdx.x >> 5);
    int l   = threadIdx.x & 31;
    const float4* in4 = (const float4*)(g_inner + (size_t)row * DIM);
    const float4* xc4 = (const float4*)(xc_g + (size_t)row * DIM);
    const float4* c14 = (const float4*)g_c1;
    const float4* c24 = (const float4*)g_c2;
    const float4* s24 = (const float4*)g_s2;

    float cu2 = g_cu2[row], x2 = g_x2c[row];
    float invdn = f_rcp(fmaxf(1.f - cu2, EPSF));
    float op = 1.f + cu2;

    float w[16], xcv[16];
    float pw2 = 0.f, pxw = 0.f;
#pragma unroll
    for (int i = 0; i < 4; i++){
        int c4 = i * 32 + l;
        float4 iv = in4[c4], xv = xc4[c4], a = c14[c4], b = c24[c4], sv = s24[c4];
        float t0 = (iv.x * a.x - op * b.x) * invdn;
        float t1 = (iv.y * a.y - op * b.y) * invdn;
        float t2 = (iv.z * a.z - op * b.z) * invdn;
        float t3 = (iv.w * a.w - op * b.w) * invdn;
        float w0 = sinh_asinh(t0, sv.x), w1 = sinh_asinh(t1, sv.y);
        float w2 = sinh_asinh(t2, sv.z), w3 = sinh_asinh(t3, sv.w);
        w[i*4+0]=w0; w[i*4+1]=w1; w[i*4+2]=w2; w[i*4+3]=w3;
        xcv[i*4+0]=xv.x; xcv[i*4+1]=xv.y; xcv[i*4+2]=xv.z; xcv[i*4+3]=xv.w;
        pw2 = fmaf(w0,w0, fmaf(w1,w1, fmaf(w2,w2, fmaf(w3,w3, pw2))));
        pxw = fmaf(xv.x,w0, fmaf(xv.y,w1, fmaf(xv.z,w2, fmaf(xv.w,w3, pxw))));
    }
#pragma unroll
    for (int o = 16; o; o >>= 1){
        pw2 += __shfl_xor_sync(0xffffffffu, pw2, o);
        pxw += __shfl_xor_sync(0xffffffffu, pxw, o);
    }
    float w2s = pw2, xw = pxw;

    float gg  = 1.f + f_sqrt(1.f + w2s);
    float rg  = f_rcp(gg);
    float yn  = f_sqrt(fmaxf(w2s * rg * rg, EPSF));
    float kv  = atanh_f(fminf(yn, CLIPA)) * f_rcp(yn);
    float step = sigmoid_f(step_p[0]);
    float m0s = step * kv * rg;
    float un  = f_sqrt(fmaxf(m0s * m0s * w2s, EPSF));
    float lam = 2.f * f_rcp(fmaxf(1.f - x2, EPSF));
    float mt  = tanh_f(0.5f * lam * un) * m0s * f_rcp(un);

    float t2s = mt * mt * w2s;
    float xt  = mt * xw;
    float pp  = 1.f + 2.f * xt + t2s;
    float qq  = 1.f - x2;
    float id2 = f_rcp(fmaxf(1.f + 2.f * xt + x2 * t2s, EPSF));
    float a1  = pp * id2, b1 = qq * mt * id2;

    float nxu2 = a1*a1*x2 + 2.f*a1*b1*xw + b1*b1*w2s;
    float nxu  = f_sqrt(fmaxf(nxu2, EPSF));
    float fxu  = (nxu > MAXN) ? MAXN * f_rcp(nxu) : 1.f;
    a1 *= fxu; b1 *= fxu;
    float nxup = fminf(nxu, MAXN);

    float nxc  = f_sqrt(fmaxf(x2, EPSF));
    float fxc  = (nxc > MAXN) ? MAXN * f_rcp(nxc) : 1.f;
    float nxcp = fminf(nxc, MAXN);

    float aa  = sigmoid_f(alpha_p[0]);
    float th1 = tanh_f(aa * atanh_f(fminf(nxcp, CLIPA)));
    float A1  = th1 * f_rcp(nxcp) * fxc;
    float th2 = tanh_f((1.f - aa) * atanh_f(fminf(nxup, CLIPA)));
    float r2  = th2 * f_rcp(nxup);
    float A2  = r2 * a1, B2 = r2 * b1;

    float x2m = th1 * th1, y2m = th2 * th2;
    float xym = A1 * (A2 * x2 + B2 * xw);
    float P   = 1.f + 2.f * xym + y2m;
    float Q   = 1.f - x2m;
    float id3 = f_rcp(fmaxf(1.f + 2.f * xym + x2m * y2m, EPSF));
    float CA  = (P * A1 + Q * A2) * id3;
    float CB  = (Q * B2) * id3;

    float nn2 = CA*CA*x2 + 2.f*CA*CB*xw + CB*CB*w2s;
    float nn  = f_sqrt(fmaxf(nn2, EPSF));
    float fo  = (nn > MAXN) ? MAXN * f_rcp(nn) : 1.f;
    CA *= fo; CB *= fo;

    float4* o1p = (float4*)(out + (size_t)row * DIM);
    float4* o2p = (float4*)(out + (size_t)BD + (size_t)row * DIM);
#pragma unroll
    for (int i = 0; i < 4; i++){
        int c4 = i * 32 + l;
        float4 o1, o2;
        o1.x = CA*xcv[i*4+0] + CB*w[i*4+0];  o2.x = fxc*xcv[i*4+0];
        o1.y = CA*xcv[i*4+1] + CB*w[i*4+1];  o2.y = fxc*xcv[i*4+1];
        o1.z = CA*xcv[i*4+2] + CB*w[i*4+2];  o2.z = fxc*xcv[i*4+2];
        o1.w = CA*xcv[i*4+3] + CB*w[i*4+3];  o2.w = fxc*xcv[i*4+3];
        o1p[c4] = o1;
        o2p[c4] = o2;
    }
}

// ------------------------------------------------------------------
// Launch: 3-stream software pipeline over 4 row-chunks (fork-join
// event pattern, graph-capturable).
//   s2: prep_rows(0..3)          (DRAM-bound)
//   s1: prep_cols, gemm(0..3)    (tensor-bound)
//   s3: finish(0..3)             (DRAM-bound), overlaps next gemm
// ------------------------------------------------------------------
extern "C" void kernel_launch(void* const* d_in, const int* in_sizes, int n_in,
                              void* d_out, int out_size) {
    const float* xc    = (const float*)d_in[0];
    const float* xp    = (const float*)d_in[1];
    const float* z     = (const float*)d_in[2];
    const float* bias  = (const float*)d_in[3];
    const float* alpha = (const float*)d_in[4];
    const float* stepz = (const float*)d_in[5];
    float* out = (float*)d_out;

    static cudaStream_t s1, s2, s3;
    static cudaEvent_t eRoot, eP[NCHUNK], eG[NCHUNK], eJ1, eJ2, eJ3;
    static int inited = 0;
    if (!inited){
        cudaStreamCreateWithFlags(&s1, cudaStreamNonBlocking);
        cudaStreamCreateWithFlags(&s2, cudaStreamNonBlocking);
        cudaStreamCreateWithFlags(&s3, cudaStreamNonBlocking);
        cudaEventCreateWithFlags(&eRoot, cudaEventDisableTiming);
        for (int m = 0; m < NCHUNK; m++){
            cudaEventCreateWithFlags(&eP[m], cudaEventDisableTiming);
            cudaEventCreateWithFlags(&eG[m], cudaEventDisableTiming);
        }
        cudaEventCreateWithFlags(&eJ1, cudaEventDisableTiming);
        cudaEventCreateWithFlags(&eJ2, cudaEventDisableTiming);
        cudaEventCreateWithFlags(&eJ3, cudaEventDisableTiming);
        cudaFuncSetAttribute(gemm_mma, cudaFuncAttributeMaxDynamicSharedMemorySize,
                             NSTAGE * STAGE_BYTES);
        inited = 1;
    }

    // fork
    cudaEventRecord(eRoot, 0);
    cudaStreamWaitEvent(s1, eRoot, 0);
    cudaStreamWaitEvent(s2, eRoot, 0);
    cudaStreamWaitEvent(s3, eRoot, 0);

    // s1: column prep (z) — upstream of all gemms by stream order
    prep_cols<<<DIM, 128, 0, s1>>>(z, bias);

    // s2: row prep per chunk
    for (int m = 0; m < NCHUNK; m++){
        prep_rows<<<CROWS / 8, 256, 0, s2>>>(xc, xp, m * CROWS);
        cudaEventRecord(eP[m], s2);
    }

    // s1: gemm per chunk (waits its chunk's prep)
    for (int m = 0; m < NCHUNK; m++){
        cudaStreamWaitEvent(s1, eP[m], 0);
        gemm_mma<<<dim3(DIM / BN, CROWS / BM), 256, NSTAGE * STAGE_BYTES, s1>>>(m * CROWS);
        cudaEventRecord(eG[m], s1);
    }

    // s3: finish per chunk (waits its chunk's gemm; overlaps next gemm)
    for (int m = 0; m < NCHUNK; m++){
        cudaStreamWaitEvent(s3, eG[m], 0);
        finish_rows<<<CROWS / 8, 256, 0, s3>>>(xc, alpha, stepz, out, m * CROWS);
    }

    // join all forked streams back to the capture/origin stream
    cudaEventRecord(eJ1, s1);
    cudaEventRecord(eJ2, s2);
    cudaEventRecord(eJ3, s3);
    cudaStreamWaitEvent(0, eJ1, 0);
    cudaStreamWaitEvent(0, eJ2, 0);
    cudaStreamWaitEvent(0, eJ3, 0);
}

// round 8
// speedup vs baseline: 1.5419x; 1.3275x over previous
#include <cuda_runtime.h>
#include <cuda_bf16.h>
#include <stdint.h>
#include <math.h>

#define B_ROWS 65536
#define DIM    512
#define KTOT   512             /* single bf16 GEMM: Uh @ Zh^T */
#define BD     (B_ROWS * DIM)
#define EPSF   1e-15f
#define MAXN   0.996f
#define CLIPA  (1.0f - 1e-7f)
#define NCHUNK 4
#define CROWS  (B_ROWS / NCHUNK)   /* 16384 */

// ------------------------------------------------------------------
// Static scratch
// ------------------------------------------------------------------
__device__ __align__(16) __nv_bfloat16 g_ub[(size_t)B_ROWS * KTOT]; // Uh [B][512]
__device__ __align__(16) __nv_bfloat16 g_zb[DIM * KTOT];            // Zh^T [out j][512]
__device__ __align__(16) float g_inner[BD];
__device__ float g_cu2[B_ROWS];
__device__ float g_x2c[B_ROWS];
__device__ __align__(16) float g_c1[DIM];
__device__ __align__(16) float g_c2[DIM];
__device__ __align__(16) float g_s2[DIM];

// ------------------------------------------------------------------
// Fast math (MUFU-based)
// ------------------------------------------------------------------
__device__ __forceinline__ float f_rcp(float x){ float y; asm("rcp.approx.f32 %0,%1;" : "=f"(y) : "f"(x)); return y; }
__device__ __forceinline__ float f_lg2(float x){ float y; asm("lg2.approx.f32 %0,%1;" : "=f"(y) : "f"(x)); return y; }
__device__ __forceinline__ float f_ex2(float x){ float y; asm("ex2.approx.f32 %0,%1;" : "=f"(y) : "f"(x)); return y; }
__device__ __forceinline__ float f_sqrt(float x){ float y; asm("sqrt.approx.f32 %0,%1;" : "=f"(y) : "f"(x)); return y; }

__device__ __forceinline__ float atanh_f(float x){
    return 0.34657359028f * f_lg2((1.f + x) * f_rcp(1.f - x));
}
__device__ __forceinline__ float tanh_f(float x){
    return 1.f - 2.f * f_rcp(f_ex2(x * 2.88539008178f) + 1.f);
}
__device__ __forceinline__ float sigmoid_f(float x){
    return f_rcp(1.f + f_ex2(-1.44269504089f * x));
}
__device__ __forceinline__ float sinh_asinh(float t, float s){
    float a = fabsf(t);
    float q = a + f_sqrt(fmaf(a, a, 1.f));
    float p = f_ex2(s * f_lg2(q));
    return copysignf(0.5f * (p - f_rcp(p)), t);
}

// ------------------------------------------------------------------
// Portable tensor-core primitives
// ------------------------------------------------------------------
__device__ __forceinline__ uint32_t s2u(const void* p){ return (uint32_t)__cvta_generic_to_shared(p); }

__device__ __forceinline__ void cp16(uint32_t dst, const void* src){
    asm volatile("cp.async.cg.shared.global [%0], [%1], 16;" :: "r"(dst), "l"(src));
}
__device__ __forceinline__ void cp_commit(){ asm volatile("cp.async.commit_group;" ::: "memory"); }
template<int N> __device__ __forceinline__ void cp_wait(){ asm volatile("cp.async.wait_group %0;" :: "n"(N) : "memory"); }

__device__ __forceinline__ void ldsm4(uint32_t* r, uint32_t addr){
    asm volatile("ldmatrix.sync.aligned.m8n8.x4.shared.b16 {%0,%1,%2,%3}, [%4];"
        : "=r"(r[0]),"=r"(r[1]),"=r"(r[2]),"=r"(r[3]) : "r"(addr));
}
__device__ __forceinline__ void mma16816(float* c, const uint32_t* a, uint32_t b0, uint32_t b1){
    asm volatile("mma.sync.aligned.m16n8k16.row.col.f32.bf16.bf16.f32 "
        "{%0,%1,%2,%3}, {%4,%5,%6,%7}, {%8,%9}, {%0,%1,%2,%3};"
        : "+f"(c[0]),"+f"(c[1]),"+f"(c[2]),"+f"(c[3])
        : "r"(a[0]),"r"(a[1]),"r"(a[2]),"r"(a[3]), "r"(b0),"r"(b1));
}

// ------------------------------------------------------------------
// Kernel 1: z stats + transposed bf16 z
// ------------------------------------------------------------------
__global__ void prep_cols(const float* __restrict__ z, const float* __restrict__ bias){
    __shared__ float sb[4];
    int j = blockIdx.x, t = threadIdx.x;
    float s = 0.f;
    for (int i = t; i < DIM; i += 128){
        float v = z[i * DIM + j];
        s += v * v;
        g_zb[j * KTOT + i] = __float2bfloat16(v);
    }
#pragma unroll
    for (int o = 16; o; o >>= 1) s += __shfl_down_sync(0xffffffffu, s, o);
    if ((t & 31) == 0) sb[t >> 5] = s;
    __syncthreads();
    if (t == 0){
        float tot = sb[0] + sb[1] + sb[2] + sb[3];
        float zn = sqrtf(fmaxf(tot, EPSF));
        float tb = 2.f * bias[j];
        g_c1[j] = 2.f * coshf(tb) / zn;
        g_c2[j] = sinhf(tb);
        g_s2[j] = 2.f * zn;
    }
}

// ------------------------------------------------------------------
// Kernel 2: warp-per-row (chunked): u -> bf16
// ------------------------------------------------------------------
__global__ void __launch_bounds__(256) prep_rows(const float* __restrict__ xc_g,
                                                 const float* __restrict__ xp_g,
                                                 int row0){
    int row = row0 + blockIdx.x * 8 + (threadIdx.x >> 5);
    int l   = threadIdx.x & 31;
    const float4* xc4 = (const float4*)(xc_g + (size_t)row * DIM);
    const float4* xp4 = (const float4*)(xp_g + (size_t)row * DIM);

    float4 xc[4], xp[4];
    float px2 = 0.f, py2 = 0.f, pxy = 0.f;
#pragma unroll
    for (int i = 0; i < 4; i++){
        xc[i] = xc4[i * 32 + l];
        xp[i] = xp4[i * 32 + l];
        px2 += xp[i].x*xp[i].x + xp[i].y*xp[i].y + xp[i].z*xp[i].z + xp[i].w*xp[i].w;
        py2 += xc[i].x*xc[i].x + xc[i].y*xc[i].y + xc[i].z*xc[i].z + xc[i].w*xc[i].w;
        pxy += xp[i].x*xc[i].x + xp[i].y*xc[i].y + xp[i].z*xc[i].z + xp[i].w*xc[i].w;
    }
#pragma unroll
    for (int o = 16; o; o >>= 1){
        px2 += __shfl_xor_sync(0xffffffffu, px2, o);
        py2 += __shfl_xor_sync(0xffffffffu, py2, o);
        pxy += __shfl_xor_sync(0xffffffffu, pxy, o);
    }
    float fA = 1.f - 2.f * pxy + py2;
    float fB = 1.f - px2;
    float invden = f_rcp(fmaxf(1.f - 2.f * pxy + px2 * py2, EPSF));

    float4 sub[4];
    float psn2 = 0.f;
#pragma unroll
    for (int i = 0; i < 4; i++){
        sub[i].x = (fB * xc[i].x - fA * xp[i].x) * invden;
        sub[i].y = (fB * xc[i].y - fA * xp[i].y) * invden;
        sub[i].z = (fB * xc[i].z - fA * xp[i].z) * invden;
        sub[i].w = (fB * xc[i].w - fA * xp[i].w) * invden;
        psn2 += sub[i].x*sub[i].x + sub[i].y*sub[i].y + sub[i].z*sub[i].z + sub[i].w*sub[i].w;
    }
#pragma unroll
    for (int o = 16; o; o >>= 1) psn2 += __shfl_xor_sync(0xffffffffu, psn2, o);
    float sn2 = psn2;
    float sn  = f_sqrt(fmaxf(sn2, EPSF));
    float c   = fmaxf(fB, EPSF) * atanh_f(fminf(sn, CLIPA)) * f_rcp(sn);
    float un  = f_sqrt(fmaxf(c * c * sn2, EPSF));
    float s   = tanh_f(un) * c * f_rcp(un);

    uint2* ub = (uint2*)(g_ub + (size_t)row * KTOT);
#pragma unroll
    for (int i = 0; i < 4; i++){
        float u0 = s*sub[i].x, u1 = s*sub[i].y, u2 = s*sub[i].z, u3 = s*sub[i].w;
        __nv_bfloat16 h0=__float2bfloat16(u0), h1=__float2bfloat16(u1),
                      h2=__float2bfloat16(u2), h3=__float2bfloat16(u3);
        uint2 hv;
        hv.x = (uint32_t)__bfloat16_as_ushort(h0) | ((uint32_t)__bfloat16_as_ushort(h1) << 16);
        hv.y = (uint32_t)__bfloat16_as_ushort(h2) | ((uint32_t)__bfloat16_as_ushort(h3) << 16);
        ub[i * 32 + l] = hv;
    }
    if (l == 0){
        g_cu2[row] = s * s * sn2;
        g_x2c[row] = py2;
    }
}

// ------------------------------------------------------------------
// Kernel 3: bf16 HMMA GEMM (chunked along M), K=512
// ------------------------------------------------------------------
#define BM 128
#define BN 256
#define BK 64
#define A_BYTES (BM*BK*2)
#define B_BYTES (BN*BK*2)
#define STAGE_BYTES (A_BYTES + B_BYTES)
#define NSTAGE 3
#define NKT (KTOT / BK)    /* 8 */

__global__ void __launch_bounds__(256, 1) gemm_mma(int row0){
    extern __shared__ __align__(128) char sm[];
    uint32_t sb = s2u(sm);
    int tid = threadIdx.x;
    int wid = tid >> 5, lane = tid & 31;
    int m0 = row0 + blockIdx.y * BM;
    int n0 = blockIdx.x * BN;
    int wm = wid & 1;
    int wn = wid >> 1;

    const char* gA = (const char*)g_ub;
    const char* gB = (const char*)g_zb;

    float acc[4][8][4];
#pragma unroll
    for (int i=0;i<4;i++)
#pragma unroll
        for (int j=0;j<8;j++)
#pragma unroll
            for (int k=0;k<4;k++) acc[i][j][k] = 0.f;

    int lr = tid >> 3;
    int lc = tid & 7;

#define LOAD_STAGE(s, kt) do {                                                 \
        uint32_t base_ = sb + (s) * STAGE_BYTES;                               \
        size_t k0_ = (size_t)(kt) * BK;                                        \
        _Pragma("unroll")                                                      \
        for (int it = 0; it < 4; it++){                                        \
            int r_ = it * 32 + lr;                                             \
            uint32_t so_ = base_ + r_ * 128 + ((lc ^ (r_ & 7)) << 4);          \
            cp16(so_, gA + ((size_t)(m0 + r_) * KTOT + k0_) * 2 + (lc << 4));  \
        }                                                                      \
        _Pragma("unroll")                                                      \
        for (int it = 0; it < 8; it++){                                        \
            int r_ = it * 32 + lr;                                             \
            uint32_t so_ = base_ + A_BYTES + r_ * 128 + ((lc ^ (r_ & 7)) << 4);\
            cp16(so_, gB + ((size_t)(n0 + r_) * KTOT + k0_) * 2 + (lc << 4));  \
        }                                                                      \
    } while (0)

    LOAD_STAGE(0, 0); cp_commit();
    LOAD_STAGE(1, 1); cp_commit();

    int lrow = lane & 15;
    int khalf = lane >> 4;

#pragma unroll 1
    for (int kt = 0; kt < NKT; kt++){
        cp_wait<1>();
        __syncthreads();
        uint32_t aBase = sb + (kt % 3) * STAGE_BYTES;
        uint32_t bBase = aBase + A_BYTES;
#pragma unroll
        for (int ks = 0; ks < 4; ks++){
            int c16 = ks * 2 + khalf;
            uint32_t a[4][4], bb[4][4];
#pragma unroll
            for (int i = 0; i < 4; i++){
                int row = wm * 64 + i * 16 + lrow;
                ldsm4(a[i], aBase + row * 128 + ((c16 ^ (row & 7)) << 4));
            }
#pragma unroll
            for (int j = 0; j < 4; j++){
                int row = wn * 64 + j * 16 + lrow;
                ldsm4(bb[j], bBase + row * 128 + ((c16 ^ (row & 7)) << 4));
            }
#pragma unroll
            for (int mi = 0; mi < 4; mi++)
#pragma unroll
                for (int ni = 0; ni < 8; ni++)
                    mma16816(acc[mi][ni], a[mi], bb[ni >> 1][ni & 1], bb[ni >> 1][(ni & 1) + 2]);
        }
        if (kt + 2 < NKT){ LOAD_STAGE((kt + 2) % 3, kt + 2); }
        cp_commit();
        __syncthreads();
    }

    int erow = lane >> 2;
    int ecol = (lane & 3) * 2;
#pragma unroll
    for (int mi = 0; mi < 4; mi++){
#pragma unroll
        for (int ni = 0; ni < 8; ni++){
            int r = m0 + wm * 64 + mi * 16 + erow;
            int c = n0 + wn * 64 + ni * 8 + ecol;
            float* p = g_inner + (size_t)r * DIM + c;
            *(float2*)p             = make_float2(acc[mi][ni][0], acc[mi][ni][1]);
            *(float2*)(p + 8 * DIM) = make_float2(acc[mi][ni][2], acc[mi][ni][3]);
        }
    }
}

// ------------------------------------------------------------------
// Kernel 4: warp-per-row epilogue (chunked)
// ------------------------------------------------------------------
__global__ void __launch_bounds__(256) finish_rows(const float* __restrict__ xc_g,
                                                   const float* __restrict__ alpha_p,
                                                   const float* __restrict__ step_p,
                                                   float* __restrict__ out,
                                                   int row0){
    int row = row0 + blockIdx.x * 8 + (threadIdx.x >> 5);
    int l   = threadIdx.x & 31;
    const float4* in4 = (const float4*)(g_inner + (size_t)row * DIM);
    const float4* xc4 = (const float4*)(xc_g + (size_t)row * DIM);
    const float4* c14 = (const float4*)g_c1;
    const float4* c24 = (const float4*)g_c2;
    const float4* s24 = (const float4*)g_s2;

    float cu2 = g_cu2[row], x2 = g_x2c[row];
    float invdn = f_rcp(fmaxf(1.f - cu2, EPSF));
    float op = 1.f + cu2;

    float w[16], xcv[16];
    float pw2 = 0.f, pxw = 0.f;
#pragma unroll
    for (int i = 0; i < 4; i++){
        int c4 = i * 32 + l;
        float4 iv = in4[c4], xv = xc4[c4], a = c14[c4], b = c24[c4], sv = s24[c4];
        float t0 = (iv.x * a.x - op * b.x) * invdn;
        float t1 = (iv.y * a.y - op * b.y) * invdn;
        float t2 = (iv.z * a.z - op * b.z) * invdn;
        float t3 = (iv.w * a.w - op * b.w) * invdn;
        float w0 = sinh_asinh(t0, sv.x), w1 = sinh_asinh(t1, sv.y);
        float w2 = sinh_asinh(t2, sv.z), w3 = sinh_asinh(t3, sv.w);
        w[i*4+0]=w0; w[i*4+1]=w1; w[i*4+2]=w2; w[i*4+3]=w3;
        xcv[i*4+0]=xv.x; xcv[i*4+1]=xv.y; xcv[i*4+2]=xv.z; xcv[i*4+3]=xv.w;
        pw2 = fmaf(w0,w0, fmaf(w1,w1, fmaf(w2,w2, fmaf(w3,w3, pw2))));
        pxw = fmaf(xv.x,w0, fmaf(xv.y,w1, fmaf(xv.z,w2, fmaf(xv.w,w3, pxw))));
    }
#pragma unroll
    for (int o = 16; o; o >>= 1){
        pw2 += __shfl_xor_sync(0xffffffffu, pw2, o);
        pxw += __shfl_xor_sync(0xffffffffu, pxw, o);
    }
    float w2s = pw2, xw = pxw;

    float gg  = 1.f + f_sqrt(1.f + w2s);
    float rg  = f_rcp(gg);
    float yn  = f_sqrt(fmaxf(w2s * rg * rg, EPSF));
    float kv  = atanh_f(fminf(yn, CLIPA)) * f_rcp(yn);
    float step = sigmoid_f(step_p[0]);
    float m0s = step * kv * rg;
    float un  = f_sqrt(fmaxf(m0s * m0s * w2s, EPSF));
    float lam = 2.f * f_rcp(fmaxf(1.f - x2, EPSF));
    float mt  = tanh_f(0.5f * lam * un) * m0s * f_rcp(un);

    float t2s = mt * mt * w2s;
    float xt  = mt * xw;
    float pp  = 1.f + 2.f * xt + t2s;
    float qq  = 1.f - x2;
    float id2 = f_rcp(fmaxf(1.f + 2.f * xt + x2 * t2s, EPSF));
    float a1  = pp * id2, b1 = qq * mt * id2;

    float nxu2 = a1*a1*x2 + 2.f*a1*b1*xw + b1*b1*w2s;
    float nxu  = f_sqrt(fmaxf(nxu2, EPSF));
    float fxu  = (nxu > MAXN) ? MAXN * f_rcp(nxu) : 1.f;
    a1 *= fxu; b1 *= fxu;
    float nxup = fminf(nxu, MAXN);

    float nxc  = f_sqrt(fmaxf(x2, EPSF));
    float fxc  = (nxc > MAXN) ? MAXN * f_rcp(nxc) : 1.f;
    float nxcp = fminf(nxc, MAXN);

    float aa  = sigmoid_f(alpha_p[0]);
    float th1 = tanh_f(aa * atanh_f(fminf(nxcp, CLIPA)));
    float A1  = th1 * f_rcp(nxcp) * fxc;
    float th2 = tanh_f((1.f - aa) * atanh_f(fminf(nxup, CLIPA)));
    float r2  = th2 * f_rcp(nxup);
    float A2  = r2 * a1, B2 = r2 * b1;

    float x2m = th1 * th1, y2m = th2 * th2;
    float xym = A1 * (A2 * x2 + B2 * xw);
    float P   = 1.f + 2.f * xym + y2m;
    float Q   = 1.f - x2m;
    float id3 = f_rcp(fmaxf(1.f + 2.f * xym + x2m * y2m, EPSF));
    float CA  = (P * A1 + Q * A2) * id3;
    float CB  = (Q * B2) * id3;

    float nn2 = CA*CA*x2 + 2.f*CA*CB*xw + CB*CB*w2s;
    float nn  = f_sqrt(fmaxf(nn2, EPSF));
    float fo  = (nn > MAXN) ? MAXN * f_rcp(nn) : 1.f;
    CA *= fo; CB *= fo;

    float4* o1p = (float4*)(out + (size_t)row * DIM);
    float4* o2p = (float4*)(out + (size_t)BD + (size_t)row * DIM);
#pragma unroll
    for (int i = 0; i < 4; i++){
        int c4 = i * 32 + l;
        float4 o1, o2;
        o1.x = CA*xcv[i*4+0] + CB*w[i*4+0];  o2.x = fxc*xcv[i*4+0];
        o1.y = CA*xcv[i*4+1] + CB*w[i*4+1];  o2.y = fxc*xcv[i*4+1];
        o1.z = CA*xcv[i*4+2] + CB*w[i*4+2];  o2.z = fxc*xcv[i*4+2];
        o1.w = CA*xcv[i*4+3] + CB*w[i*4+3];  o2.w = fxc*xcv[i*4+3];
        o1p[c4] = o1;
        o2p[c4] = o2;
    }
}

// ------------------------------------------------------------------
// Launch: 3-stream software pipeline over 4 row-chunks
// ------------------------------------------------------------------
extern "C" void kernel_launch(void* const* d_in, const int* in_sizes, int n_in,
                              void* d_out, int out_size) {
    const float* xc    = (const float*)d_in[0];
    const float* xp    = (const float*)d_in[1];
    const float* z     = (const float*)d_in[2];
    const float* bias  = (const float*)d_in[3];
    const float* alpha = (const float*)d_in[4];
    const float* stepz = (const float*)d_in[5];
    float* out = (float*)d_out;

    static cudaStream_t s1, s2, s3;
    static cudaEvent_t eRoot, eP[NCHUNK], eG[NCHUNK], eJ1, eJ2, eJ3;
    static int inited = 0;
    if (!inited){
        cudaStreamCreateWithFlags(&s1, cudaStreamNonBlocking);
        cudaStreamCreateWithFlags(&s2, cudaStreamNonBlocking);
        cudaStreamCreateWithFlags(&s3, cudaStreamNonBlocking);
        cudaEventCreateWithFlags(&eRoot, cudaEventDisableTiming);
        for (int m = 0; m < NCHUNK; m++){
            cudaEventCreateWithFlags(&eP[m], cudaEventDisableTiming);
            cudaEventCreateWithFlags(&eG[m], cudaEventDisableTiming);
        }
        cudaEventCreateWithFlags(&eJ1, cudaEventDisableTiming);
        cudaEventCreateWithFlags(&eJ2, cudaEventDisableTiming);
        cudaEventCreateWithFlags(&eJ3, cudaEventDisableTiming);
        cudaFuncSetAttribute(gemm_mma, cudaFuncAttributeMaxDynamicSharedMemorySize,
                             NSTAGE * STAGE_BYTES);
        inited = 1;
    }

    // fork
    cudaEventRecord(eRoot, 0);
    cudaStreamWaitEvent(s1, eRoot, 0);
    cudaStreamWaitEvent(s2, eRoot, 0);
    cudaStreamWaitEvent(s3, eRoot, 0);

    // s1: column prep (z)
    prep_cols<<<DIM, 128, 0, s1>>>(z, bias);

    // s2: row prep per chunk
    for (int m = 0; m < NCHUNK; m++){
        prep_rows<<<CROWS / 8, 256, 0, s2>>>(xc, xp, m * CROWS);
        cudaEventRecord(eP[m], s2);
    }

    // s1: gemm per chunk
    for (int m = 0; m < NCHUNK; m++){
        cudaStreamWaitEvent(s1, eP[m], 0);
        gemm_mma<<<dim3(DIM / BN, CROWS / BM), 256, NSTAGE * STAGE_BYTES, s1>>>(m * CROWS);
        cudaEventRecord(eG[m], s1);
    }

    // s3: finish per chunk
    for (int m = 0; m < NCHUNK; m++){
        cudaStreamWaitEvent(s3, eG[m], 0);
        finish_rows<<<CROWS / 8, 256, 0, s3>>>(xc, alpha, stepz, out, m * CROWS);
    }

    // join
    cudaEventRecord(eJ1, s1);
    cudaEventRecord(eJ2, s2);
    cudaEventRecord(eJ3, s3);
    cudaStreamWaitEvent(0, eJ1, 0);
    cudaStreamWaitEvent(0, eJ2, 0);
    cudaStreamWaitEvent(0, eJ3, 0);
}